// round 12
// baseline (speedup 1.0000x reference)
#include <cuda_runtime.h>
#include <math.h>

#define H_    96
#define W_    128
#define C_    21
#define RAD   16
#define TAPS  33
#define PADH  (H_ + 2*RAD)     // 128 padded rows per channel
#define PPW   168              // padded row stride for hconv (>= 164)
#define GRID  96
#define NT    672              // 21 warps

// Scratch (__device__ globals: allocation-free rule)
__device__ float g_tmp[2][C_*PADH*W_];   // halo-padded, double-buffered hconv out

// channel split over 4 groups: sizes 6,5,5,5
__device__ __forceinline__ int grp_c0(int g)  { return (g == 0) ? 0 : (1 + 5*g); }
__device__ __forceinline__ int grp_len(int g) { return (g == 0) ? 6 : 5; }

// hconv: all 672 threads; warp = channel, 4 outputs/thread, sliding reg window.
__device__ __forceinline__ void hconv_store(const float* pp, const float* skx,
                                            float* dst, int t)
{
    const int c  = t >> 5;
    const int x0 = (t & 31) << 2;
    const float* p = pp + c*PPW + x0;      // out r = sum_j skx[j] * p[j+r]
    float a0=0.f, a1=0.f, a2=0.f, a3=0.f;
    float b0 = p[0], b1 = p[1], b2 = p[2];
    #pragma unroll
    for (int j = 0; j < TAPS; j++) {
        float b3 = p[j+3];
        float k = skx[j];
        a0 += k*b0; a1 += k*b1; a2 += k*b2; a3 += k*b3;
        b0 = b1; b1 = b2; b2 = b3;
    }
    *(float4*)&dst[c*PADH*W_ + x0] = make_float4(a0, a1, a2, a3);
}

// ---------------- A0: zero halos + softmax(unaries) + hconv -> buf0 ----------------
__global__ __launch_bounds__(NT)
void k_a0(const float* __restrict__ un)
{
    __shared__ float skx[TAPS];
    __shared__ float s_un[C_*W_];
    __shared__ float pp[C_*PPW];
    __shared__ float s_red[4*W_];
    __shared__ float s_m[W_];
    const int t = threadIdx.x, y = blockIdx.x;

    if (t < TAPS) skx[t] = __expf(-(float)((t-RAD)*(t-RAD)) / 18.0f);
    if (t < C_*(PPW - W_)) {                       // zero hconv pads (840)
        int c = t / (PPW - W_), k = t % (PPW - W_);
        pp[c*PPW + (k < RAD ? k : W_ + k)] = 0.f;
    }
    // zero this block's share of both buffers' halo rows (2*21*32*128 / 96 = 1792)
    for (int i = t; i < 1792; i += NT) {
        int gidx = y*1792 + i;
        int buf  = gidx / (C_*2*RAD*W_);
        int rem  = gidx % (C_*2*RAD*W_);
        int c    = rem / (2*RAD*W_);
        int rr   = (rem / W_) % (2*RAD);
        int w    = rem % W_;
        int row  = (rr < RAD) ? rr : (H_ + rr);    // top 16 / bottom 16 rows
        g_tmp[buf][(c*PADH + row)*W_ + w] = 0.f;
    }
    {   // stage unaries row: un[y][x][c] -> s_un[c*W + x]
        const float* ub = un + y*W_*C_;
        for (int i = t; i < C_*W_; i += NT) {
            int x = i / C_, c = i - x*C_;
            s_un[c*W_ + x] = ub[i];
        }
    }
    __syncthreads();

    // parallel softmax over channels (512 threads hold q in regs)
    int x = 0, g = 0, c0 = 0, ln = 0;
    float q[6];
    if (t < 512) {
        x = t & 127; g = t >> 7; c0 = grp_c0(g); ln = grp_len(g);
        float pm = -1e30f;
        #pragma unroll 6
        for (int ci = 0; ci < 6; ci++) {
            if (ci >= ln) break;
            q[ci] = s_un[(c0 + ci)*W_ + x];
            pm = fmaxf(pm, q[ci]);
        }
        s_red[g*W_ + x] = pm;
    }
    __syncthreads();
    if (t < W_)
        s_m[t] = fmaxf(fmaxf(s_red[t], s_red[W_+t]), fmaxf(s_red[2*W_+t], s_red[3*W_+t]));
    __syncthreads();
    if (t < 512) {
        float m = s_m[x], ps = 0.f;
        #pragma unroll 6
        for (int ci = 0; ci < 6; ci++) {
            if (ci >= ln) break;
            q[ci] = __expf(q[ci] - m); ps += q[ci];
        }
        s_red[g*W_ + x] = ps;
    }
    __syncthreads();
    if (t < W_)
        s_m[t] = 1.0f / (s_red[t] + s_red[W_+t] + s_red[2*W_+t] + s_red[3*W_+t]);
    __syncthreads();
    if (t < 512) {
        float inv = s_m[x];
        #pragma unroll 6
        for (int ci = 0; ci < 6; ci++) {
            if (ci >= ln) break;
            pp[(c0 + ci)*PPW + RAD + x] = q[ci] * inv;
        }
    }
    __syncthreads();
    hconv_store(pp, skx, &g_tmp[0][(RAD + y)*W_], t);
}

// ------- B: vconv + update matvec (+ softmax + hconv | final out) -------
__global__ __launch_bounds__(NT)
void k_b(const float* __restrict__ un,
         const float* __restrict__ ws,
         const float* __restrict__ wbw,
         const float* __restrict__ compat,
         float* __restrict__ out, int rb, int final_it)
{
    __shared__ float skx[TAPS];
    __shared__ float sinx[W_];
    __shared__ float sA[C_*C_];
    __shared__ float s_un[C_*W_];
    __shared__ float s_sv[C_*W_];
    __shared__ float pp[C_*PPW];
    __shared__ float s_red[4*W_];
    __shared__ float s_m[W_];
    __shared__ float s_ny;

    const int t = threadIdx.x, y = blockIdx.x;

    if (t < TAPS) skx[t] = __expf(-(float)((t-RAD)*(t-RAD)) / 18.0f);
    if (!final_it && t < C_*(PPW - W_)) {          // zero hconv pads
        int c = t / (PPW - W_), k = t % (PPW - W_);
        pp[c*PPW + (k < RAD ? k : W_ + k)] = 0.f;
    }
    if (t < C_*C_) {                               // sA = compat @ (Ws + Wb)
        int i = t / C_, j = t % C_;                // bilateral path dead (source bug)
        float a = 0.f;
        #pragma unroll
        for (int k = 0; k < C_; k++)
            a += compat[i*C_ + k] * (ws[k*C_ + j] + wbw[k*C_ + j]);
        sA[t] = a;
    }
    {   // stage unaries row
        const float* ub = un + y*W_*C_;
        for (int i = t; i < C_*W_; i += NT) {
            int x = i / C_, c = i - x*C_;
            s_un[c*W_ + x] = ub[i];
        }
    }
    __syncthreads();
    if (t < W_) {                                  // sinx (needs skx)
        float s = 0.f;
        #pragma unroll
        for (int j = 0; j < TAPS; j++) {
            int xp = t + j - RAD;
            if (xp >= 0 && xp < W_) s += skx[j];
        }
        sinx[t] = 1.0f / s;
    }
    if (t == 512) {                                // siny for this row
        float s = 0.f;
        #pragma unroll
        for (int j = 0; j < TAPS; j++) {
            int yp = y + j - RAD;
            if (yp >= 0 && yp < H_) s += skx[j];
        }
        s_ny = 1.0f / s;
    }
    __syncthreads();

    // vconv: warp = channel, lane = float4 column; halo rows are zero (no branches)
    {
        const int c  = t >> 5;
        const int x4 = (t & 31) << 2;
        const float4* src = (const float4*)&g_tmp[rb][(c*PADH + y)*W_ + x4];
        float4 acc = make_float4(0.f, 0.f, 0.f, 0.f);
        #pragma unroll
        for (int j = 0; j < TAPS; j++) {
            float4 v = src[j*(W_/4)];
            float k = skx[j];
            acc.x += k*v.x; acc.y += k*v.y; acc.z += k*v.z; acc.w += k*v.w;
        }
        const float nys = s_ny;
        s_sv[c*W_ + x4 + 0] = acc.x * (sinx[x4 + 0] * nys);
        s_sv[c*W_ + x4 + 1] = acc.y * (sinx[x4 + 1] * nys);
        s_sv[c*W_ + x4 + 2] = acc.z * (sinx[x4 + 2] * nys);
        s_sv[c*W_ + x4 + 3] = acc.w * (sinx[x4 + 3] * nys);
    }
    __syncthreads();

    // update matvec: q = u - A*s (512 threads: pixel x, channel group g)
    int x = 0, g = 0, c0 = 0, ln = 0;
    float q[6];
    if (t < 512) {
        x = t & 127; g = t >> 7; c0 = grp_c0(g); ln = grp_len(g);
        #pragma unroll 6
        for (int ci = 0; ci < 6; ci++) {
            if (ci >= ln) break;
            q[ci] = s_un[(c0 + ci)*W_ + x];
        }
        #pragma unroll
        for (int cp = 0; cp < C_; cp++) {
            float s0 = s_sv[cp*W_ + x];
            #pragma unroll 6
            for (int ci = 0; ci < 6; ci++) {
                if (ci >= ln) break;
                q[ci] -= sA[(c0 + ci)*C_ + cp] * s0;
            }
        }
    }
    if (final_it) {
        if (t < 512) {
            #pragma unroll 6
            for (int ci = 0; ci < 6; ci++) {
                if (ci >= ln) break;
                out[(x*H_ + y)*C_ + c0 + ci] = q[ci];   // out[0, w, h, c]
            }
        }
        return;
    }

    // parallel softmax on q (regs) -> pp
    if (t < 512) {
        float pm = -1e30f;
        #pragma unroll 6
        for (int ci = 0; ci < 6; ci++) {
            if (ci >= ln) break;
            pm = fmaxf(pm, q[ci]);
        }
        s_red[g*W_ + x] = pm;
    }
    __syncthreads();
    if (t < W_)
        s_m[t] = fmaxf(fmaxf(s_red[t], s_red[W_+t]), fmaxf(s_red[2*W_+t], s_red[3*W_+t]));
    __syncthreads();
    if (t < 512) {
        float m = s_m[x], ps = 0.f;
        #pragma unroll 6
        for (int ci = 0; ci < 6; ci++) {
            if (ci >= ln) break;
            q[ci] = __expf(q[ci] - m); ps += q[ci];
        }
        s_red[g*W_ + x] = ps;
    }
    __syncthreads();
    if (t < W_)
        s_m[t] = 1.0f / (s_red[t] + s_red[W_+t] + s_red[2*W_+t] + s_red[3*W_+t]);
    __syncthreads();
    if (t < 512) {
        float inv = s_m[x];
        #pragma unroll 6
        for (int ci = 0; ci < 6; ci++) {
            if (ci >= ln) break;
            pp[(c0 + ci)*PPW + RAD + x] = q[ci] * inv;
        }
    }
    __syncthreads();

    hconv_store(pp, skx, &g_tmp[rb ^ 1][(RAD + y)*W_], t);
}

extern "C" void kernel_launch(void* const* d_in, const int* in_sizes, int n_in,
                              void* d_out, int out_size) {
    const float* un     = (const float*)d_in[0];
    // d_in[1] = rgb : provably unused (bilateral output discarded by replicated source bug)
    const float* ws     = (const float*)d_in[2];
    const float* wb     = (const float*)d_in[3];
    const float* compat = (const float*)d_in[4];
    float* out = (float*)d_out;

    k_a0<<<GRID, NT>>>(un);
    k_b<<<GRID, NT>>>(un, ws, wb, compat, out, 0, 0);   // it1: buf0 -> buf1
    k_b<<<GRID, NT>>>(un, ws, wb, compat, out, 1, 0);   // it2
    k_b<<<GRID, NT>>>(un, ws, wb, compat, out, 0, 0);   // it3
    k_b<<<GRID, NT>>>(un, ws, wb, compat, out, 1, 0);   // it4
    k_b<<<GRID, NT>>>(un, ws, wb, compat, out, 0, 1);   // it5 final -> out
}